// round 2
// baseline (speedup 1.0000x reference)
#include <cuda_runtime.h>
#include <math.h>

#define BB 1024
#define SS 100
#define HH 512
#define GG 1536   // 3*H
#define NUSR 1000

// Scratch (device globals: allowed; no runtime allocation)
__device__ float g_xproj[(size_t)BB * SS * GG];   // [B,S,3H]
__device__ float g_gruout[(size_t)BB * SS * HH];  // [B,S,H] (unmasked)

// ---------------------------------------------------------------------------
// Kernel 1: x_proj[M=B*S, N=3H] = X[M,512] @ W_ih^T + b_ih
// 128x128x8 tiled fp32 GEMM, 256 threads, 8x8 per thread, prefetch gmem->reg.
// ---------------------------------------------------------------------------
__global__ void __launch_bounds__(256, 2)
k_xproj(const float* __restrict__ X, const float* __restrict__ W,
        const float* __restrict__ bias) {
    __shared__ float As[8][128];
    __shared__ float Bs[8][128];
    const int tid = threadIdx.x;
    const int tx = tid & 15;
    const int ty = tid >> 4;
    const int bm = blockIdx.x;   // 0..799
    const int bn = blockIdx.y;   // 0..11
    const int r  = tid >> 1;     // 0..127 local row
    const int q  = (tid & 1) * 4;

    const float* Ap = X + (size_t)(bm * 128 + r) * 512 + q;
    const float* Bp = W + (size_t)(bn * 128 + r) * 512 + q;

    float acc[8][8];
#pragma unroll
    for (int i = 0; i < 8; i++)
#pragma unroll
        for (int j = 0; j < 8; j++) acc[i][j] = 0.f;

    float4 av = *(const float4*)Ap;
    float4 bv = *(const float4*)Bp;

    for (int kt = 0; kt < 64; kt++) {
        __syncthreads();
        As[q + 0][r] = av.x; As[q + 1][r] = av.y; As[q + 2][r] = av.z; As[q + 3][r] = av.w;
        Bs[q + 0][r] = bv.x; Bs[q + 1][r] = bv.y; Bs[q + 2][r] = bv.z; Bs[q + 3][r] = bv.w;
        __syncthreads();
        if (kt < 63) {
            av = *(const float4*)(Ap + (kt + 1) * 8);
            bv = *(const float4*)(Bp + (kt + 1) * 8);
        }
#pragma unroll
        for (int k = 0; k < 8; k++) {
            float4 a0 = *(const float4*)&As[k][ty * 8];
            float4 a1 = *(const float4*)&As[k][ty * 8 + 4];
            float4 b0 = *(const float4*)&Bs[k][tx * 8];
            float4 b1 = *(const float4*)&Bs[k][tx * 8 + 4];
            float a[8] = {a0.x, a0.y, a0.z, a0.w, a1.x, a1.y, a1.z, a1.w};
            float b[8] = {b0.x, b0.y, b0.z, b0.w, b1.x, b1.y, b1.z, b1.w};
#pragma unroll
            for (int i = 0; i < 8; i++)
#pragma unroll
                for (int j = 0; j < 8; j++) acc[i][j] += a[i] * b[j];
        }
    }

    const int n0 = bn * 128 + tx * 8;
    float bias8[8];
#pragma unroll
    for (int j = 0; j < 8; j++) bias8[j] = bias[n0 + j];
#pragma unroll
    for (int i = 0; i < 8; i++) {
        int m = bm * 128 + ty * 8 + i;
        float* o = g_xproj + (size_t)m * GG + n0;
        float4 v0, v1;
        v0.x = acc[i][0] + bias8[0]; v0.y = acc[i][1] + bias8[1];
        v0.z = acc[i][2] + bias8[2]; v0.w = acc[i][3] + bias8[3];
        v1.x = acc[i][4] + bias8[4]; v1.y = acc[i][5] + bias8[5];
        v1.z = acc[i][6] + bias8[6]; v1.w = acc[i][7] + bias8[7];
        *(float4*)(o)     = v0;
        *(float4*)(o + 4) = v1;
    }
}

// ---------------------------------------------------------------------------
// Kernel 2: GRU recurrence. Each CTA owns 8 batch rows and runs all 100 steps.
// Per step: gh[8,1536] = h[8,512] @ W_hh^T  (W_hh streamed through SMEM in
// k-tiles of 8 with register prefetch), then fused gate epilogue.
// Dynamic SMEM: h_s[8][513] + w_s[8][1536] + gh_s[8][1536] = 114,720 B.
// ---------------------------------------------------------------------------
#define SMEM_GRU_BYTES ((8 * 513 + 8 * 1536 + 8 * 1536) * 4)

__global__ void __launch_bounds__(256, 1)
k_gru(const float* __restrict__ h0, const float* __restrict__ Whh,
      const float* __restrict__ bhh) {
    extern __shared__ float sm[];
    float* h_s  = sm;                 // [8][513]
    float* w_s  = sm + 8 * 513;       // [8 k][1536 n]
    float* gh_s = w_s + 8 * 1536;     // [8 m][1536 n]
    const int tid = threadIdx.x;
    const int b0 = blockIdx.x * 8;

    for (int idx = tid; idx < 8 * 512; idx += 256) {
        int m = idx >> 9, j = idx & 511;
        h_s[m * 513 + j] = h0[(size_t)(b0 + m) * 512 + j];
    }
    float bh[6];
#pragma unroll
    for (int j = 0; j < 6; j++) bh[j] = bhh[tid + 256 * j];
    __syncthreads();

    for (int t = 0; t < SS; t++) {
        float acc[8][6];
#pragma unroll
        for (int m = 0; m < 8; m++)
#pragma unroll
            for (int j = 0; j < 6; j++) acc[m][j] = 0.f;

        // prefetch k-tile 0 of W_hh (12 float4 per thread cover 1536x8 tile)
        float4 vb[12];
#pragma unroll
        for (int j = 0; j < 12; j++) {
            int id = tid + 256 * j;
            vb[j] = *(const float4*)(Whh + (size_t)(id >> 1) * 512 + ((id & 1) << 2));
        }

        for (int kt = 0; kt < 64; kt++) {
            __syncthreads();
#pragma unroll
            for (int j = 0; j < 12; j++) {
                int id = tid + 256 * j;
                int rr = id >> 1, qq = (id & 1) * 4;
                w_s[(qq + 0) * 1536 + rr] = vb[j].x;
                w_s[(qq + 1) * 1536 + rr] = vb[j].y;
                w_s[(qq + 2) * 1536 + rr] = vb[j].z;
                w_s[(qq + 3) * 1536 + rr] = vb[j].w;
            }
            __syncthreads();
            if (kt < 63) {
#pragma unroll
                for (int j = 0; j < 12; j++) {
                    int id = tid + 256 * j;
                    vb[j] = *(const float4*)(Whh + (size_t)(id >> 1) * 512 +
                                             (kt + 1) * 8 + ((id & 1) << 2));
                }
            }
#pragma unroll
            for (int k = 0; k < 8; k++) {
                float a[8];
#pragma unroll
                for (int m = 0; m < 8; m++) a[m] = h_s[m * 513 + kt * 8 + k];
                float w[6];
#pragma unroll
                for (int j = 0; j < 6; j++) w[j] = w_s[k * 1536 + tid + 256 * j];
#pragma unroll
                for (int m = 0; m < 8; m++)
#pragma unroll
                    for (int j = 0; j < 6; j++) acc[m][j] += a[m] * w[j];
            }
        }
        __syncthreads();
#pragma unroll
        for (int m = 0; m < 8; m++)
#pragma unroll
            for (int j = 0; j < 6; j++)
                gh_s[m * 1536 + tid + 256 * j] = acc[m][j] + bh[j];
        __syncthreads();

        // gates
        for (int idx = tid; idx < 8 * 512; idx += 256) {
            int m = idx >> 9, j = idx & 511;
            const float* xp = g_xproj + ((size_t)((b0 + m) * SS + t)) * GG;
            float xr = xp[j], xz = xp[512 + j], xn = xp[1024 + j];
            float hr = gh_s[m * 1536 + j];
            float hz = gh_s[m * 1536 + 512 + j];
            float hn = gh_s[m * 1536 + 1024 + j];
            float rg = 1.f / (1.f + expf(-(xr + hr)));
            float zg = 1.f / (1.f + expf(-(xz + hz)));
            float ng = tanhf(xn + rg * hn);
            float hv = h_s[m * 513 + j];
            float hnew = (1.f - zg) * ng + zg * hv;
            h_s[m * 513 + j] = hnew;
            g_gruout[((size_t)(b0 + m) * SS + t) * HH + j] = hnew;
        }
        __syncthreads();
    }
}

// ---------------------------------------------------------------------------
// Kernel 3: per-batch-row attention + softmax + weighted pooling.
// One CTA per b. Masked GRU output (mask applied to hidden vec, per reference)
// cached in SMEM [100][513]; Wa_b streamed in 64-o x 16-k tiles.
// scores[s] = sum_o Ws[o]*tanh(E[s,o]+ba[o])   (bs dropped: softmax-invariant)
// Dynamic SMEM: 100*513 + 16*64 + 128 floats = 209,808 B.
// ---------------------------------------------------------------------------
#define SMEM_ATTN_BYTES ((100 * 513 + 16 * 64 + 128) * 4)

__global__ void __launch_bounds__(256, 1)
k_attn(const float* __restrict__ reps, const int* __restrict__ counts,
       const int* __restrict__ users, const float* __restrict__ Wa,
       const float* __restrict__ ba, const float* __restrict__ Wsv,
       float* __restrict__ outp) {
    extern __shared__ float sm[];
    float* out_s = sm;                  // [100][513]
    float* Bsm   = sm + 100 * 513;      // [16 k][64 o]
    float* score = Bsm + 16 * 64;       // [128]
    const int tid = threadIdx.x;
    const int b = blockIdx.x;
    const int cnt = counts[b];
    const int u = users[b];

    for (int idx = tid; idx < 100 * 512; idx += 256) {
        int s = idx >> 9, h = idx & 511;
        float v = g_gruout[((size_t)b * SS + s) * HH + h];
        if (s >= cnt) v -= 1000000.0f;
        out_s[s * 513 + h] = v;
    }
    if (tid < 128) score[tid] = 0.f;
    __syncthreads();

    const int tx = tid & 15;   // o-group (4 cols each)
    const int ty = tid >> 4;   // s-group (7 rows each)
    int srow[7];
#pragma unroll
    for (int i = 0; i < 7; i++) {
        int s = ty * 7 + i;
        srow[i] = (s < 100 ? s : 99) * 513;
    }
    const float* WaU = Wa + (size_t)u * (512 * 512);
    const int rB = tid >> 2;
    const int qB = (tid & 3) * 4;

    for (int c = 0; c < 8; c++) {
        float acc[7][4];
#pragma unroll
        for (int i = 0; i < 7; i++)
#pragma unroll
            for (int j = 0; j < 4; j++) acc[i][j] = 0.f;

        const float* wp = WaU + (size_t)(c * 64 + rB) * 512 + qB;
        float4 v = *(const float4*)wp;

        for (int kt = 0; kt < 32; kt++) {
            __syncthreads();
            Bsm[(qB + 0) * 64 + rB] = v.x;
            Bsm[(qB + 1) * 64 + rB] = v.y;
            Bsm[(qB + 2) * 64 + rB] = v.z;
            Bsm[(qB + 3) * 64 + rB] = v.w;
            __syncthreads();
            if (kt < 31) v = *(const float4*)(wp + (kt + 1) * 16);
#pragma unroll
            for (int k = 0; k < 16; k++) {
                float a[7];
#pragma unroll
                for (int i = 0; i < 7; i++) a[i] = out_s[srow[i] + kt * 16 + k];
                float4 wv = *(const float4*)&Bsm[k * 64 + tx * 4];
#pragma unroll
                for (int i = 0; i < 7; i++) {
                    acc[i][0] += a[i] * wv.x;
                    acc[i][1] += a[i] * wv.y;
                    acc[i][2] += a[i] * wv.z;
                    acc[i][3] += a[i] * wv.w;
                }
            }
        }
        float ba4[4], ws4[4];
#pragma unroll
        for (int j = 0; j < 4; j++) {
            int o = c * 64 + tx * 4 + j;
            ba4[j] = ba[(size_t)u * 512 + o];
            ws4[j] = Wsv[(size_t)u * 512 + o];
        }
#pragma unroll
        for (int i = 0; i < 7; i++) {
            int s = ty * 7 + i;
            if (s < 100) {
                float p = 0.f;
#pragma unroll
                for (int j = 0; j < 4; j++) p += ws4[j] * tanhf(acc[i][j] + ba4[j]);
                atomicAdd(&score[s], p);
            }
        }
    }
    __syncthreads();

    // softmax over 100 scores (warp 0)
    if (tid < 32) {
        float mx = -1e30f;
        for (int s = tid; s < 100; s += 32) mx = fmaxf(mx, score[s]);
#pragma unroll
        for (int o = 16; o > 0; o >>= 1) mx = fmaxf(mx, __shfl_xor_sync(0xffffffffu, mx, o));
        float ssum = 0.f;
        for (int s = tid; s < 100; s += 32) {
            float e = expf(score[s] - mx);
            score[s] = e;
            ssum += e;
        }
#pragma unroll
        for (int o = 16; o > 0; o >>= 1) ssum += __shfl_xor_sync(0xffffffffu, ssum, o);
        float inv = 1.f / ssum;
        for (int s = tid; s < 100; s += 32) score[s] *= inv;
    }
    __syncthreads();

    // user_repr = sum_s attn[s] * reps[b,s,:]
    const float* rb = reps + (size_t)b * (SS * HH);
    for (int h = tid; h < 512; h += 256) {
        float a0 = 0.f;
        for (int s = 0; s < 100; s++) a0 += score[s] * rb[s * 512 + h];
        outp[(size_t)b * 512 + h] = a0;
    }
}

// ---------------------------------------------------------------------------
extern "C" void kernel_launch(void* const* d_in, const int* in_sizes, int n_in,
                              void* d_out, int out_size) {
    const float* reps   = (const float*)d_in[0];
    const float* hidden = (const float*)d_in[1];
    const int*   counts = (const int*)d_in[2];
    const int*   users  = (const int*)d_in[3];
    const float* W_ih   = (const float*)d_in[4];
    const float* W_hh   = (const float*)d_in[5];
    const float* b_ih   = (const float*)d_in[6];
    const float* b_hh   = (const float*)d_in[7];
    const float* Wa     = (const float*)d_in[8];
    const float* ba     = (const float*)d_in[9];
    const float* Ws     = (const float*)d_in[10];
    // d_in[11] = bs: additive per-row constant on scores -> softmax-invariant.
    float* out = (float*)d_out;

    cudaFuncSetAttribute(k_gru, cudaFuncAttributeMaxDynamicSharedMemorySize,
                         SMEM_GRU_BYTES);
    cudaFuncSetAttribute(k_attn, cudaFuncAttributeMaxDynamicSharedMemorySize,
                         SMEM_ATTN_BYTES);

    dim3 g1(800, 12);
    k_xproj<<<g1, 256>>>(reps, W_ih, b_ih);
    k_gru<<<BB / 8, 256, SMEM_GRU_BYTES>>>(hidden, W_hh, b_hh);
    k_attn<<<BB, 256, SMEM_ATTN_BYTES>>>(reps, counts, users, Wa, ba, Ws, out);
}